// round 12
// baseline (speedup 1.0000x reference)
#include <cuda_runtime.h>
#include <stdint.h>

#define BB 4
#define AA 3
#define HH 168
#define WW 256
#define NN (HH*WW*AA)     // 129024
#define MM 32
#define NBINS 1024
#define CAPB 160
#define NPI 256
#define NPOSMAX 128
#define FG 0.7f
#define BG 0.3f
#define BETA (1.0f/9.0f)
#define CB 512            // colmax block size

// ------- scratch (device globals; zero at load; re-zeroed by select's last block)
__device__ unsigned            d_colmax[BB*MM];
__device__ int                 d_nin[BB];                 // compact inside-anchor count
__device__ float4              d_cA  [(size_t)BB*NN];     // compact anchors
__device__ int                 d_cIdx[(size_t)BB*NN];     // compact original index
__device__ int                 d_pcnt[BB*NBINS];
__device__ int                 d_ncnt[BB*NBINS];
__device__ float               d_psc [BB*NBINS];
__device__ float               d_psr [BB*NBINS];
__device__ float               d_nsc [BB*NBINS];
__device__ unsigned long long  d_pkey[(size_t)BB*NBINS*CAPB];
__device__ unsigned long long  d_nkey[(size_t)BB*NBINS*CAPB];
__device__ float               d_pvc [(size_t)BB*NBINS*CAPB];
__device__ float               d_pvr [(size_t)BB*NBINS*CAPB];
__device__ float               d_nvc [(size_t)BB*NBINS*CAPB];
__device__ float               d_ocls[2*BB];
__device__ float               d_oreg[2*BB];
__device__ int                 d_ocnt[2*BB];
__device__ int                 d_done;

// ---------------- threefry2x32 (exact JAX rotation/injection schedule) ------
__device__ __forceinline__ void tf2x32(unsigned k0, unsigned k1,
                                       unsigned x0, unsigned x1,
                                       unsigned &o0, unsigned &o1) {
    unsigned k2 = k0 ^ k1 ^ 0x1BD11BDAu;
    x0 += k0; x1 += k1;
#define TF_RND(r) { x0 += x1; x1 = (x1<<(r))|(x1>>(32-(r))); x1 ^= x0; }
    TF_RND(13) TF_RND(15) TF_RND(26) TF_RND(6)   x0 += k1; x1 += k2 + 1u;
    TF_RND(17) TF_RND(29) TF_RND(16) TF_RND(24)  x0 += k2; x1 += k0 + 2u;
    TF_RND(13) TF_RND(15) TF_RND(26) TF_RND(6)   x0 += k0; x1 += k1 + 3u;
    TF_RND(17) TF_RND(29) TF_RND(16) TF_RND(24)  x0 += k1; x1 += k2 + 4u;
    TF_RND(13) TF_RND(15) TF_RND(26) TF_RND(6)   x0 += k2; x1 += k0 + 5u;
#undef TF_RND
    o0 = x0; o1 = x1;
}

__device__ __forceinline__ float barea(float x1, float y1, float x2, float y2) {
    return __fmul_rn(__fadd_rn(__fsub_rn(x2, x1), 1.0f),
                     __fadd_rn(__fsub_rn(y2, y1), 1.0f));
}

// ------- kernel 1: per-target column max of IoU + inside-anchor compaction ---
__global__ __launch_bounds__(CB) void k_colmax(const float* __restrict__ anchors,
                                               const float* __restrict__ targets,
                                               const float* __restrict__ sizes) {
    const int BLK = NN / CB;          // 252
    int b = blockIdx.x / BLK;
    int tile = (blockIdx.x % BLK) * CB;
    int t = threadIdx.x, lane = t & 31, w = t >> 5;   // w: 0..15

    __shared__ float4 sA[CB];
    __shared__ float  sAr[CB];

    float4 A0 = reinterpret_cast<const float4*>(anchors)[(size_t)b*NN + tile + t];
    sA[t] = A0;
    sAr[t] = barea(A0.x, A0.y, A0.z, A0.w);

    // inside-anchor compaction (colmax itself uses ALL anchors, per reference)
    {
        float szh = __ldg(&sizes[b*2]), szw = __ldg(&sizes[b*2 + 1]);
        bool inside = (A0.x >= 0.f) && (A0.y >= 0.f) &&
                      (A0.z <= szw - 1.0f) && (A0.w <= szh - 1.0f);
        unsigned m = __ballot_sync(0xFFFFFFFFu, inside);
        int cnt = __popc(m);
        if (cnt) {
            int base0 = 0;
            if (lane == 0) base0 = atomicAdd(&d_nin[b], cnt);
            base0 = __shfl_sync(0xFFFFFFFFu, base0, 0);
            if (inside) {
                int pos = base0 + __popc(m & ((1u << lane) - 1u));
                d_cA  [(size_t)b*NN + pos] = A0;
                d_cIdx[(size_t)b*NN + pos] = tile + t;
            }
        }
    }
    __syncthreads();

    float4 T0 = __ldg(&reinterpret_cast<const float4*>(targets)[b*MM + w*2 + 0]);
    float4 T1 = __ldg(&reinterpret_cast<const float4*>(targets)[b*MM + w*2 + 1]);
    float Tar0 = barea(T0.x, T0.y, T0.z, T0.w);
    float Tar1 = barea(T1.x, T1.y, T1.z, T1.w);
    float bi0 = 0.f, bu0 = 1.f, bi1 = 0.f, bu1 = 1.f;

    #pragma unroll 4
    for (int a = 0; a < CB/32; a++) {
        float4 X  = sA [a*32 + lane];
        float xar = sAr[a*32 + lane];
        {
            float iw = __fadd_rn(__fsub_rn(fminf(X.z, T0.z), fmaxf(X.x, T0.x)), 1.0f);
            float ih = __fadd_rn(__fsub_rn(fminf(X.w, T0.w), fmaxf(X.y, T0.y)), 1.0f);
            float inter = __fmul_rn(fmaxf(iw, 0.f), fmaxf(ih, 0.f));
            float u = __fsub_rn(__fadd_rn(xar, Tar0), inter);
            if (inter*bu0 > bi0*u) { bi0 = inter; bu0 = u; }
        }
        {
            float iw = __fadd_rn(__fsub_rn(fminf(X.z, T1.z), fmaxf(X.x, T1.x)), 1.0f);
            float ih = __fadd_rn(__fsub_rn(fminf(X.w, T1.w), fmaxf(X.y, T1.y)), 1.0f);
            float inter = __fmul_rn(fmaxf(iw, 0.f), fmaxf(ih, 0.f));
            float u = __fsub_rn(__fadd_rn(xar, Tar1), inter);
            if (inter*bu1 > bi1*u) { bi1 = inter; bu1 = u; }
        }
    }

    // margin epilogue: approx div + warp fmax; candidates do exact div + atomic
    {
        float qa = (bi0 > 0.f) ? __fdividef(bi0, bu0) : 0.f;
        float m = qa;
        #pragma unroll
        for (int off = 16; off; off >>= 1)
            m = fmaxf(m, __shfl_xor_sync(0xFFFFFFFFu, m, off));
        if (bi0 > 0.f && qa >= __fmul_rn(m, 0.999998f)) {
            float q = __fdiv_rn(bi0, bu0);
            atomicMax(&d_colmax[b*MM + w*2 + 0], __float_as_uint(q));
        }
    }
    {
        float qa = (bi1 > 0.f) ? __fdividef(bi1, bu1) : 0.f;
        float m = qa;
        #pragma unroll
        for (int off = 16; off; off >>= 1)
            m = fmaxf(m, __shfl_xor_sync(0xFFFFFFFFu, m, off));
        if (bi1 > 0.f && qa >= __fmul_rn(m, 0.999998f)) {
            float q = __fdiv_rn(bi1, bu1);
            atomicMax(&d_colmax[b*MM + w*2 + 1], __float_as_uint(q));
        }
    }
}

// ---------------- kernel 2: classify compacted inside anchors ---------------
__global__ void k_classify(const float* __restrict__ logits,
                           const float* __restrict__ bregs,
                           const float* __restrict__ targets) {
    const int BLK = NN / 256;
    int b = blockIdx.x / BLK;
    int slot = (blockIdx.x % BLK) * 256 + threadIdx.x;

    __shared__ float4 stt[MM];
    __shared__ float  star[MM], slo[MM];
    __shared__ unsigned scol[MM];
    __shared__ uint2 skeyb;
    __shared__ int sanyz, scnt2;
    if (threadIdx.x == 0) {
        unsigned o0, o1;
        tf2x32(0u, 42u, 0u, (unsigned)b, o0, o1);   // fold-like split of key 42
        skeyb = make_uint2(o0, o1);
        sanyz = 0;
        scnt2 = d_nin[b];
    }
    if (threadIdx.x < MM) {
        float4 t = reinterpret_cast<const float4*>(targets)[b*MM + threadIdx.x];
        stt[threadIdx.x] = t;
        star[threadIdx.x] = barea(t.x, t.y, t.z, t.w);
        unsigned cb = d_colmax[b*MM + threadIdx.x];
        scol[threadIdx.x] = cb;
        slo[threadIdx.x] = __fmul_rn(__uint_as_float(cb), 0.999998f);
        if (cb == 0u) sanyz = 1;                    // benign race (all write 1)
    }
    __syncthreads();

    if (slot >= scnt2) return;                      // past compacted count
    float4 A = d_cA[(size_t)b*NN + slot];
    int i = d_cIdx[(size_t)b*NN + slot];

    bool restore = (sanyz != 0);
    float aar = barea(A.x, A.y, A.z, A.w);
    float bi = 0.f, bu = 1.f; int ori = 0;

    #pragma unroll 8
    for (int j = 0; j < MM; j++) {
        float4 T = stt[j];
        float iw = __fadd_rn(__fsub_rn(fminf(A.z, T.z), fmaxf(A.x, T.x)), 1.0f);
        float ih = __fadd_rn(__fsub_rn(fminf(A.w, T.w), fmaxf(A.y, T.y)), 1.0f);
        float inter = __fmul_rn(fmaxf(iw, 0.f), fmaxf(ih, 0.f));
        float u = __fsub_rn(__fadd_rn(aar, star[j]), inter);
        if (inter*bu > bi*u) { bi = inter; bu = u; ori = j; }
        if (inter > 0.f && inter >= __fmul_rn(slo[j], u)) {  // rare: exact div
            float q = __fdiv_rn(inter, u);
            restore = restore || (__float_as_uint(q) == scol[j]);
        }
    }
    float best = (bi > 0.f) ? __fdiv_rn(bi, bu) : 0.f;  // RN monotone

    bool pos = (best >= FG) || restore;
    bool neg = (!restore) && (best < BG);
    if (!pos && !neg) return;

    // exact JAX uniform priority: bits = o0^o1 of threefry(key_b, (0, i))
    unsigned o0, o1;
    tf2x32(skeyb.x, skeyb.y, 0u, (unsigned)i, o0, o1);
    unsigned prio = (o0 ^ o1) >> 9;
    unsigned long long kk = ((unsigned long long)prio << 32) | (0xFFFFFFFFu - (unsigned)i);
    int bin = (int)(prio >> 13);                    // 1024 bins

    int ai = i % AA; int hw = i / AA; int wx = hw % WW; int hy = hw / WW;
    float l = logits[(((size_t)b*AA + ai)*HH + hy)*WW + wx];
    float sp = log1pf(expf(-fabsf(l)));
    float cls = fmaxf(l, 0.f) + sp;          // BCE(l, 0)

    if (pos) {
        cls -= l;                            // BCE(l, 1)
        float ws = A.z - A.x + 1.0f, hs = A.w - A.y + 1.0f;
        float xc = A.x + 0.5f*ws,   yc = A.y + 0.5f*hs;
        float4 T = stt[ori];
        float tws = T.z - T.x + 1.0f, ths = T.w - T.y + 1.0f;
        float txc = T.x + 0.5f*tws,  tyc = T.y + 0.5f*ths;
        float off[4] = { (txc - xc)/ws, (tyc - yc)/hs, logf(tws/ws), logf(ths/hs) };
        float reg = 0.f;
        #pragma unroll
        for (int c = 0; c < 4; c++) {
            float br = bregs[(((size_t)b*4*AA + ai*4 + c)*HH + hy)*WW + wx];
            float d = fabsf(br - off[c]);
            reg += (d < BETA) ? 0.5f*d*d/BETA : d - 0.5f*BETA;
        }
        int idx = b*NBINS + bin;
        int c0 = atomicAdd(&d_pcnt[idx], 1);
        atomicAdd(&d_psc[idx], cls);
        atomicAdd(&d_psr[idx], reg);
        if (c0 < CAPB) {
            size_t e = (size_t)idx*CAPB + c0;
            d_pkey[e] = kk; d_pvc[e] = cls; d_pvr[e] = reg;
        }
    } else {
        int idx = b*NBINS + bin;
        int c0 = atomicAdd(&d_ncnt[idx], 1);
        atomicAdd(&d_nsc[idx], cls);
        if (c0 < CAPB) {
            size_t e = (size_t)idx*CAPB + c0;
            d_nkey[e] = kk; d_nvc[e] = cls;
        }
    }
}

// -------- kernel 3: exact top-K selection + finalize + scratch re-zero ------
__global__ void k_select2(float* __restrict__ out) {
    int b  = blockIdx.x >> 1;
    int ph = blockIdx.x & 1;           // 0 = positives, 1 = negatives
    int t = threadIdx.x;
    int lane = t & 31, wid = t >> 5;

    __shared__ int   scnt[NBINS];
    __shared__ float sred[256];
    __shared__ int   swsum[8];
    __shared__ int   sint[4];
    __shared__ unsigned long long skey[CAPB];
    __shared__ float sv1[CAPB], sv2[CAPB];
    __shared__ int slast;

    const int*   cnt = (ph ? d_ncnt : d_pcnt) + b*NBINS;
    const float* s1  = (ph ? d_nsc  : d_psc ) + b*NBINS;
    const float* s2  = d_psr + b*NBINS;
    const unsigned long long* keyg = (ph ? d_nkey : d_pkey) + (size_t)b*NBINS*CAPB;
    const float* v1g = (ph ? d_nvc : d_pvc) + (size_t)b*NBINS*CAPB;
    const float* v2g = d_pvr + (size_t)b*NBINS*CAPB;

    int K;
    if (ph == 0) {
        K = NPOSMAX;
    } else {
        // num_pos = min(total positives, NPOSMAX): 1024 ints = 1 int4/thread
        int4 c = ((const int4*)(d_pcnt + b*NBINS))[t];
        int s = c.x + c.y + c.z + c.w;
        #pragma unroll
        for (int off = 16; off; off >>= 1) s += __shfl_xor_sync(0xFFFFFFFFu, s, off);
        if (lane == 0) swsum[wid] = s;
        __syncthreads();
        if (t == 0) { int tot = 0; for (int w = 0; w < 8; w++) tot += swsum[w]; sint[3] = tot; }
        __syncthreads();
        int np = sint[3]; if (np > NPOSMAX) np = NPOSMAX;
        K = NPI - np;
        __syncthreads();
    }

    // thread t owns 4 bins [base, base+4), base descending with t
    int base = NBINS - 4*(t+1);
    int4 c4 = *(const int4*)(cnt + base);
    scnt[base+0] = c4.x; scnt[base+1] = c4.y; scnt[base+2] = c4.z; scnt[base+3] = c4.w;
    int cs = c4.x + c4.y + c4.z + c4.w;

    int v = cs;
    #pragma unroll
    for (int off = 1; off < 32; off <<= 1) {
        int n = __shfl_up_sync(0xFFFFFFFFu, v, off);
        if (lane >= off) v += n;
    }
    if (lane == 31) swsum[wid] = v;
    __syncthreads();
    if (t < 8) {
        int x = swsum[t];
        #pragma unroll
        for (int off = 1; off < 8; off <<= 1) {
            int n = __shfl_up_sync(0x000000FFu, x, off);
            if (t >= off) x += n;
        }
        swsum[t] = x;
    }
    __syncthreads();
    int incl  = v + (wid ? swsum[wid-1] : 0);
    int excl  = incl - cs;
    int total = swsum[7];

    if (t == 0) { sint[0] = -1; sint[1] = 0; }
    __syncthreads();
    if (total > K && excl < K && incl >= K) {     // exactly one thread
        int cum = excl;
        #pragma unroll
        for (int k = 3; k >= 0; k--) {            // descending bin order
            int cc = scnt[base + k];
            if (cum + cc >= K) { sint[0] = base + k; sint[1] = K - cum; break; }
            cum += cc;
        }
    }
    __syncthreads();
    int binT = sint[0], Kp = sint[1];

    // whole-bin sums for bins strictly above the threshold bin
    float a1 = 0.f, a2 = 0.f;
    {
        float4 x = *(const float4*)(s1 + base);
        if (base + 0 > binT) a1 += x.x;
        if (base + 1 > binT) a1 += x.y;
        if (base + 2 > binT) a1 += x.z;
        if (base + 3 > binT) a1 += x.w;
        if (ph == 0) {
            float4 y = *(const float4*)(s2 + base);
            if (base + 0 > binT) a2 += y.x;
            if (base + 1 > binT) a2 += y.y;
            if (base + 2 > binT) a2 += y.z;
            if (base + 3 > binT) a2 += y.w;
        }
    }

    // boundary bin: exact rank selection on unique keys
    if (binT >= 0) {
        int nt = cnt[binT]; if (nt > CAPB) nt = CAPB;
        size_t bb2 = (size_t)binT * CAPB;
        for (int e = t; e < nt; e += 256) {
            skey[e] = keyg[bb2 + e];
            sv1[e]  = v1g[bb2 + e];
            if (ph == 0) sv2[e] = v2g[bb2 + e];
        }
        __syncthreads();
        for (int e = t; e < nt; e += 256) {
            unsigned long long ke = skey[e];
            int rank = 0;
            for (int q = 0; q < nt; q++) rank += (skey[q] > ke);
            if (rank < Kp) { a1 += sv1[e]; if (ph == 0) a2 += sv2[e]; }
        }
    }
    __syncthreads();

    sred[t] = a1; __syncthreads();
    #pragma unroll
    for (int off = 128; off; off >>= 1) { if (t < off) sred[t] += sred[t + off]; __syncthreads(); }
    float r1 = sred[0];
    __syncthreads();
    sred[t] = a2; __syncthreads();
    #pragma unroll
    for (int off = 128; off; off >>= 1) { if (t < off) sred[t] += sred[t + off]; __syncthreads(); }
    float r2 = sred[0];

    if (t == 0) {
        d_ocls[blockIdx.x] = r1;
        d_oreg[blockIdx.x] = (ph == 0) ? r2 : 0.f;
        d_ocnt[blockIdx.x] = (total < K) ? total : K;
        __threadfence();
        int done = atomicAdd(&d_done, 1);
        slast = (done == 2*BB - 1);
    }
    __syncthreads();

    // last block: finalize output + restore scratch to zero for the next replay
    if (slast) {
        __threadfence();
        int4 zi = make_int4(0,0,0,0);
        float4 zf = make_float4(0.f,0.f,0.f,0.f);
        #pragma unroll
        for (int g = 0; g < (BB*NBINS/4)/256; g++) {
            int idx = g*256 + t;
            reinterpret_cast<int4*>(d_pcnt)[idx]   = zi;
            reinterpret_cast<int4*>(d_ncnt)[idx]   = zi;
            reinterpret_cast<float4*>(d_psc)[idx]  = zf;
            reinterpret_cast<float4*>(d_psr)[idx]  = zf;
            reinterpret_cast<float4*>(d_nsc)[idx]  = zf;
        }
        if (t < BB*MM) d_colmax[t] = 0u;
        if (t < BB) d_nin[t] = 0;
        if (t == 0) {
            d_done = 0;
            float cs = 0.f, rs = 0.f; int cn = 0;
            #pragma unroll
            for (int q = 0; q < 2*BB; q++) { cs += d_ocls[q]; rs += d_oreg[q]; cn += d_ocnt[q]; }
            float tot = (float)cn;
            out[0] = cs / tot;
            out[1] = rs / tot;
        }
    }
}

// ---------------- launch ----------------------------------------------------
extern "C" void kernel_launch(void* const* d_in, const int* in_sizes, int n_in,
                              void* d_out, int out_size) {
    const float* anchors = (const float*)d_in[0];
    const float* logits  = (const float*)d_in[1];
    const float* bregs   = (const float*)d_in[2];
    const float* sizes   = (const float*)d_in[3];
    const float* targets = (const float*)d_in[4];
    float* out = (float*)d_out;

    k_colmax<<<BB*(NN/CB), CB>>>(anchors, targets, sizes);
    k_classify<<<BB*(NN/256), 256>>>(logits, bregs, targets);
    k_select2<<<2*BB, 256>>>(out);
}

// round 13
// speedup vs baseline: 1.1112x; 1.1112x over previous
#include <cuda_runtime.h>
#include <stdint.h>

#define BB 4
#define AA 3
#define HH 168
#define WW 256
#define NN (HH*WW*AA)     // 129024
#define MM 32
#define NBINS 1024
#define CAPB 160
#define NPI 256
#define NPOSMAX 128
#define FG 0.7f
#define BG 0.3f
#define BETA (1.0f/9.0f)
#define CB 512            // colmax block size

// ------- scratch (device globals; zero at load; re-zeroed by select's last block)
__device__ unsigned            d_colmax[BB*MM];
__device__ int                 d_nin[BB];                 // compact inside-anchor count
__device__ float4              d_cA  [(size_t)BB*NN];     // compact anchors
__device__ int                 d_cIdx[(size_t)BB*NN];     // compact original index
__device__ int                 d_pcnt[BB*NBINS];
__device__ int                 d_ncnt[BB*NBINS];
__device__ float               d_psc [BB*NBINS];
__device__ float               d_psr [BB*NBINS];
__device__ float               d_nsc [BB*NBINS];
__device__ unsigned long long  d_pkey[(size_t)BB*NBINS*CAPB];
__device__ unsigned long long  d_nkey[(size_t)BB*NBINS*CAPB];
__device__ float               d_pvc [(size_t)BB*NBINS*CAPB];
__device__ float               d_pvr [(size_t)BB*NBINS*CAPB];
__device__ float               d_nvc [(size_t)BB*NBINS*CAPB];
__device__ float               d_ocls[2*BB];
__device__ float               d_oreg[2*BB];
__device__ int                 d_ocnt[2*BB];
__device__ int                 d_done;

// ---------------- threefry2x32 (exact JAX rotation/injection schedule) ------
__device__ __forceinline__ void tf2x32(unsigned k0, unsigned k1,
                                       unsigned x0, unsigned x1,
                                       unsigned &o0, unsigned &o1) {
    unsigned k2 = k0 ^ k1 ^ 0x1BD11BDAu;
    x0 += k0; x1 += k1;
#define TF_RND(r) { x0 += x1; x1 = (x1<<(r))|(x1>>(32-(r))); x1 ^= x0; }
    TF_RND(13) TF_RND(15) TF_RND(26) TF_RND(6)   x0 += k1; x1 += k2 + 1u;
    TF_RND(17) TF_RND(29) TF_RND(16) TF_RND(24)  x0 += k2; x1 += k0 + 2u;
    TF_RND(13) TF_RND(15) TF_RND(26) TF_RND(6)   x0 += k0; x1 += k1 + 3u;
    TF_RND(17) TF_RND(29) TF_RND(16) TF_RND(24)  x0 += k1; x1 += k2 + 4u;
    TF_RND(13) TF_RND(15) TF_RND(26) TF_RND(6)   x0 += k2; x1 += k0 + 5u;
#undef TF_RND
    o0 = x0; o1 = x1;
}

__device__ __forceinline__ float barea(float x1, float y1, float x2, float y2) {
    return __fmul_rn(__fadd_rn(__fsub_rn(x2, x1), 1.0f),
                     __fadd_rn(__fsub_rn(y2, y1), 1.0f));
}

// ------- kernel 1: per-target column max of IoU + inside-anchor compaction ---
// Hot loop identical to the 21.2us R10 version; compaction moved to the kernel
// tail with ONE block-level atomic (smem warp-count scan) instead of per-warp
// contended atomics.
__global__ __launch_bounds__(CB) void k_colmax(const float* __restrict__ anchors,
                                               const float* __restrict__ targets,
                                               const float* __restrict__ sizes) {
    const int BLK = NN / CB;          // 252
    int b = blockIdx.x / BLK;
    int tile = (blockIdx.x % BLK) * CB;
    int t = threadIdx.x, lane = t & 31, w = t >> 5;   // w: 0..15

    __shared__ float4 sA[CB];
    __shared__ float  sAr[CB];
    __shared__ int    swoff[CB/32];
    __shared__ int    sbase;

    float4 A0 = reinterpret_cast<const float4*>(anchors)[(size_t)b*NN + tile + t];
    sA[t] = A0;
    sAr[t] = barea(A0.x, A0.y, A0.z, A0.w);
    __syncthreads();

    float4 T0 = __ldg(&reinterpret_cast<const float4*>(targets)[b*MM + w*2 + 0]);
    float4 T1 = __ldg(&reinterpret_cast<const float4*>(targets)[b*MM + w*2 + 1]);
    float Tar0 = barea(T0.x, T0.y, T0.z, T0.w);
    float Tar1 = barea(T1.x, T1.y, T1.z, T1.w);
    float bi0 = 0.f, bu0 = 1.f, bi1 = 0.f, bu1 = 1.f;

    #pragma unroll 4
    for (int a = 0; a < CB/32; a++) {
        float4 X  = sA [a*32 + lane];
        float xar = sAr[a*32 + lane];
        {
            float iw = __fadd_rn(__fsub_rn(fminf(X.z, T0.z), fmaxf(X.x, T0.x)), 1.0f);
            float ih = __fadd_rn(__fsub_rn(fminf(X.w, T0.w), fmaxf(X.y, T0.y)), 1.0f);
            float inter = __fmul_rn(fmaxf(iw, 0.f), fmaxf(ih, 0.f));
            float u = __fsub_rn(__fadd_rn(xar, Tar0), inter);
            if (inter*bu0 > bi0*u) { bi0 = inter; bu0 = u; }
        }
        {
            float iw = __fadd_rn(__fsub_rn(fminf(X.z, T1.z), fmaxf(X.x, T1.x)), 1.0f);
            float ih = __fadd_rn(__fsub_rn(fminf(X.w, T1.w), fmaxf(X.y, T1.y)), 1.0f);
            float inter = __fmul_rn(fmaxf(iw, 0.f), fmaxf(ih, 0.f));
            float u = __fsub_rn(__fadd_rn(xar, Tar1), inter);
            if (inter*bu1 > bi1*u) { bi1 = inter; bu1 = u; }
        }
    }

    // margin epilogue: approx div + warp fmax; candidates do exact div + atomic
    {
        float qa = (bi0 > 0.f) ? __fdividef(bi0, bu0) : 0.f;
        float m = qa;
        #pragma unroll
        for (int off = 16; off; off >>= 1)
            m = fmaxf(m, __shfl_xor_sync(0xFFFFFFFFu, m, off));
        if (bi0 > 0.f && qa >= __fmul_rn(m, 0.999998f)) {
            float q = __fdiv_rn(bi0, bu0);
            atomicMax(&d_colmax[b*MM + w*2 + 0], __float_as_uint(q));
        }
    }
    {
        float qa = (bi1 > 0.f) ? __fdividef(bi1, bu1) : 0.f;
        float m = qa;
        #pragma unroll
        for (int off = 16; off; off >>= 1)
            m = fmaxf(m, __shfl_xor_sync(0xFFFFFFFFu, m, off));
        if (bi1 > 0.f && qa >= __fmul_rn(m, 0.999998f)) {
            float q = __fdiv_rn(bi1, bu1);
            atomicMax(&d_colmax[b*MM + w*2 + 1], __float_as_uint(q));
        }
    }

    // tail: inside-anchor compaction, one atomic per block
    float szh = __ldg(&sizes[b*2]), szw = __ldg(&sizes[b*2 + 1]);
    bool inside = (A0.x >= 0.f) && (A0.y >= 0.f) &&
                  (A0.z <= szw - 1.0f) && (A0.w <= szh - 1.0f);
    unsigned m = __ballot_sync(0xFFFFFFFFu, inside);
    if (lane == 0) swoff[w] = __popc(m);
    __syncthreads();
    if (t == 0) {
        int tot = 0;
        #pragma unroll
        for (int k = 0; k < CB/32; k++) { int c = swoff[k]; swoff[k] = tot; tot += c; }
        sbase = atomicAdd(&d_nin[b], tot);
    }
    __syncthreads();
    if (inside) {
        int pos = sbase + swoff[w] + __popc(m & ((1u << lane) - 1u));
        d_cA  [(size_t)b*NN + pos] = A0;
        d_cIdx[(size_t)b*NN + pos] = tile + t;
    }
}

// ---------------- kernel 2: classify compacted inside anchors ---------------
__global__ void k_classify(const float* __restrict__ logits,
                           const float* __restrict__ bregs,
                           const float* __restrict__ targets) {
    const int BLK = NN / 256;
    int b = blockIdx.x / BLK;
    int slot = (blockIdx.x % BLK) * 256 + threadIdx.x;

    __shared__ float4 stt[MM];
    __shared__ float  star[MM], slo[MM];
    __shared__ unsigned scol[MM];
    __shared__ uint2 skeyb;
    __shared__ int sanyz, scnt2;
    if (threadIdx.x == 0) {
        unsigned o0, o1;
        tf2x32(0u, 42u, 0u, (unsigned)b, o0, o1);   // fold-like split of key 42
        skeyb = make_uint2(o0, o1);
        sanyz = 0;
        scnt2 = d_nin[b];
    }
    if (threadIdx.x < MM) {
        float4 t = reinterpret_cast<const float4*>(targets)[b*MM + threadIdx.x];
        stt[threadIdx.x] = t;
        star[threadIdx.x] = barea(t.x, t.y, t.z, t.w);
        unsigned cb = d_colmax[b*MM + threadIdx.x];
        scol[threadIdx.x] = cb;
        slo[threadIdx.x] = __fmul_rn(__uint_as_float(cb), 0.999998f);
        if (cb == 0u) sanyz = 1;                    // benign race (all write 1)
    }
    __syncthreads();

    if (slot >= scnt2) return;                      // past compacted count
    float4 A = d_cA[(size_t)b*NN + slot];
    int i = d_cIdx[(size_t)b*NN + slot];

    bool restore = (sanyz != 0);
    float aar = barea(A.x, A.y, A.z, A.w);
    float bi = 0.f, bu = 1.f; int ori = 0;

    #pragma unroll 8
    for (int j = 0; j < MM; j++) {
        float4 T = stt[j];
        float iw = __fadd_rn(__fsub_rn(fminf(A.z, T.z), fmaxf(A.x, T.x)), 1.0f);
        float ih = __fadd_rn(__fsub_rn(fminf(A.w, T.w), fmaxf(A.y, T.y)), 1.0f);
        float inter = __fmul_rn(fmaxf(iw, 0.f), fmaxf(ih, 0.f));
        float u = __fsub_rn(__fadd_rn(aar, star[j]), inter);
        if (inter*bu > bi*u) { bi = inter; bu = u; ori = j; }
        if (inter > 0.f && inter >= __fmul_rn(slo[j], u)) {  // rare: exact div
            float q = __fdiv_rn(inter, u);
            restore = restore || (__float_as_uint(q) == scol[j]);
        }
    }
    float best = (bi > 0.f) ? __fdiv_rn(bi, bu) : 0.f;  // RN monotone

    bool pos = (best >= FG) || restore;
    bool neg = (!restore) && (best < BG);
    if (!pos && !neg) return;

    // exact JAX uniform priority: bits = o0^o1 of threefry(key_b, (0, i))
    unsigned o0, o1;
    tf2x32(skeyb.x, skeyb.y, 0u, (unsigned)i, o0, o1);
    unsigned prio = (o0 ^ o1) >> 9;
    unsigned long long kk = ((unsigned long long)prio << 32) | (0xFFFFFFFFu - (unsigned)i);
    int bin = (int)(prio >> 13);                    // 1024 bins

    int ai = i % AA; int hw = i / AA; int wx = hw % WW; int hy = hw / WW;
    float l = logits[(((size_t)b*AA + ai)*HH + hy)*WW + wx];
    float sp = log1pf(expf(-fabsf(l)));
    float cls = fmaxf(l, 0.f) + sp;          // BCE(l, 0)

    if (pos) {
        cls -= l;                            // BCE(l, 1)
        float ws = A.z - A.x + 1.0f, hs = A.w - A.y + 1.0f;
        float xc = A.x + 0.5f*ws,   yc = A.y + 0.5f*hs;
        float4 T = stt[ori];
        float tws = T.z - T.x + 1.0f, ths = T.w - T.y + 1.0f;
        float txc = T.x + 0.5f*tws,  tyc = T.y + 0.5f*ths;
        float off[4] = { (txc - xc)/ws, (tyc - yc)/hs, logf(tws/ws), logf(ths/hs) };
        float reg = 0.f;
        #pragma unroll
        for (int c = 0; c < 4; c++) {
            float br = bregs[(((size_t)b*4*AA + ai*4 + c)*HH + hy)*WW + wx];
            float d = fabsf(br - off[c]);
            reg += (d < BETA) ? 0.5f*d*d/BETA : d - 0.5f*BETA;
        }
        int idx = b*NBINS + bin;
        int c0 = atomicAdd(&d_pcnt[idx], 1);
        atomicAdd(&d_psc[idx], cls);
        atomicAdd(&d_psr[idx], reg);
        if (c0 < CAPB) {
            size_t e = (size_t)idx*CAPB + c0;
            d_pkey[e] = kk; d_pvc[e] = cls; d_pvr[e] = reg;
        }
    } else {
        int idx = b*NBINS + bin;
        int c0 = atomicAdd(&d_ncnt[idx], 1);
        atomicAdd(&d_nsc[idx], cls);
        if (c0 < CAPB) {
            size_t e = (size_t)idx*CAPB + c0;
            d_nkey[e] = kk; d_nvc[e] = cls;
        }
    }
}

// -------- kernel 3: exact top-K selection + finalize + scratch re-zero ------
__global__ void k_select2(float* __restrict__ out) {
    int b  = blockIdx.x >> 1;
    int ph = blockIdx.x & 1;           // 0 = positives, 1 = negatives
    int t = threadIdx.x;
    int lane = t & 31, wid = t >> 5;

    __shared__ int   scnt[NBINS];
    __shared__ float sred[256];
    __shared__ int   swsum[8];
    __shared__ int   sint[4];
    __shared__ unsigned long long skey[CAPB];
    __shared__ float sv1[CAPB], sv2[CAPB];
    __shared__ int slast;

    const int*   cnt = (ph ? d_ncnt : d_pcnt) + b*NBINS;
    const float* s1  = (ph ? d_nsc  : d_psc ) + b*NBINS;
    const float* s2  = d_psr + b*NBINS;
    const unsigned long long* keyg = (ph ? d_nkey : d_pkey) + (size_t)b*NBINS*CAPB;
    const float* v1g = (ph ? d_nvc : d_pvc) + (size_t)b*NBINS*CAPB;
    const float* v2g = d_pvr + (size_t)b*NBINS*CAPB;

    int K;
    if (ph == 0) {
        K = NPOSMAX;
    } else {
        // num_pos = min(total positives, NPOSMAX): 1024 ints = 1 int4/thread
        int4 c = ((const int4*)(d_pcnt + b*NBINS))[t];
        int s = c.x + c.y + c.z + c.w;
        #pragma unroll
        for (int off = 16; off; off >>= 1) s += __shfl_xor_sync(0xFFFFFFFFu, s, off);
        if (lane == 0) swsum[wid] = s;
        __syncthreads();
        if (t == 0) { int tot = 0; for (int w = 0; w < 8; w++) tot += swsum[w]; sint[3] = tot; }
        __syncthreads();
        int np = sint[3]; if (np > NPOSMAX) np = NPOSMAX;
        K = NPI - np;
        __syncthreads();
    }

    // thread t owns 4 bins [base, base+4), base descending with t
    int base = NBINS - 4*(t+1);
    int4 c4 = *(const int4*)(cnt + base);
    scnt[base+0] = c4.x; scnt[base+1] = c4.y; scnt[base+2] = c4.z; scnt[base+3] = c4.w;
    int cs = c4.x + c4.y + c4.z + c4.w;

    int v = cs;
    #pragma unroll
    for (int off = 1; off < 32; off <<= 1) {
        int n = __shfl_up_sync(0xFFFFFFFFu, v, off);
        if (lane >= off) v += n;
    }
    if (lane == 31) swsum[wid] = v;
    __syncthreads();
    if (t < 8) {
        int x = swsum[t];
        #pragma unroll
        for (int off = 1; off < 8; off <<= 1) {
            int n = __shfl_up_sync(0x000000FFu, x, off);
            if (t >= off) x += n;
        }
        swsum[t] = x;
    }
    __syncthreads();
    int incl  = v + (wid ? swsum[wid-1] : 0);
    int excl  = incl - cs;
    int total = swsum[7];

    if (t == 0) { sint[0] = -1; sint[1] = 0; }
    __syncthreads();
    if (total > K && excl < K && incl >= K) {     // exactly one thread
        int cum = excl;
        #pragma unroll
        for (int k = 3; k >= 0; k--) {            // descending bin order
            int cc = scnt[base + k];
            if (cum + cc >= K) { sint[0] = base + k; sint[1] = K - cum; break; }
            cum += cc;
        }
    }
    __syncthreads();
    int binT = sint[0], Kp = sint[1];

    // whole-bin sums for bins strictly above the threshold bin
    float a1 = 0.f, a2 = 0.f;
    {
        float4 x = *(const float4*)(s1 + base);
        if (base + 0 > binT) a1 += x.x;
        if (base + 1 > binT) a1 += x.y;
        if (base + 2 > binT) a1 += x.z;
        if (base + 3 > binT) a1 += x.w;
        if (ph == 0) {
            float4 y = *(const float4*)(s2 + base);
            if (base + 0 > binT) a2 += y.x;
            if (base + 1 > binT) a2 += y.y;
            if (base + 2 > binT) a2 += y.z;
            if (base + 3 > binT) a2 += y.w;
        }
    }

    // boundary bin: exact rank selection on unique keys
    if (binT >= 0) {
        int nt = cnt[binT]; if (nt > CAPB) nt = CAPB;
        size_t bb2 = (size_t)binT * CAPB;
        for (int e = t; e < nt; e += 256) {
            skey[e] = keyg[bb2 + e];
            sv1[e]  = v1g[bb2 + e];
            if (ph == 0) sv2[e] = v2g[bb2 + e];
        }
        __syncthreads();
        for (int e = t; e < nt; e += 256) {
            unsigned long long ke = skey[e];
            int rank = 0;
            for (int q = 0; q < nt; q++) rank += (skey[q] > ke);
            if (rank < Kp) { a1 += sv1[e]; if (ph == 0) a2 += sv2[e]; }
        }
    }
    __syncthreads();

    sred[t] = a1; __syncthreads();
    #pragma unroll
    for (int off = 128; off; off >>= 1) { if (t < off) sred[t] += sred[t + off]; __syncthreads(); }
    float r1 = sred[0];
    __syncthreads();
    sred[t] = a2; __syncthreads();
    #pragma unroll
    for (int off = 128; off; off >>= 1) { if (t < off) sred[t] += sred[t + off]; __syncthreads(); }
    float r2 = sred[0];

    if (t == 0) {
        d_ocls[blockIdx.x] = r1;
        d_oreg[blockIdx.x] = (ph == 0) ? r2 : 0.f;
        d_ocnt[blockIdx.x] = (total < K) ? total : K;
        __threadfence();
        int done = atomicAdd(&d_done, 1);
        slast = (done == 2*BB - 1);
    }
    __syncthreads();

    // last block: finalize output + restore scratch to zero for the next replay
    if (slast) {
        __threadfence();
        int4 zi = make_int4(0,0,0,0);
        float4 zf = make_float4(0.f,0.f,0.f,0.f);
        #pragma unroll
        for (int g = 0; g < (BB*NBINS/4)/256; g++) {
            int idx = g*256 + t;
            reinterpret_cast<int4*>(d_pcnt)[idx]   = zi;
            reinterpret_cast<int4*>(d_ncnt)[idx]   = zi;
            reinterpret_cast<float4*>(d_psc)[idx]  = zf;
            reinterpret_cast<float4*>(d_psr)[idx]  = zf;
            reinterpret_cast<float4*>(d_nsc)[idx]  = zf;
        }
        if (t < BB*MM) d_colmax[t] = 0u;
        if (t < BB) d_nin[t] = 0;
        if (t == 0) {
            d_done = 0;
            float cs = 0.f, rs = 0.f; int cn = 0;
            #pragma unroll
            for (int q = 0; q < 2*BB; q++) { cs += d_ocls[q]; rs += d_oreg[q]; cn += d_ocnt[q]; }
            float tot = (float)cn;
            out[0] = cs / tot;
            out[1] = rs / tot;
        }
    }
}

// ---------------- launch ----------------------------------------------------
extern "C" void kernel_launch(void* const* d_in, const int* in_sizes, int n_in,
                              void* d_out, int out_size) {
    const float* anchors = (const float*)d_in[0];
    const float* logits  = (const float*)d_in[1];
    const float* bregs   = (const float*)d_in[2];
    const float* sizes   = (const float*)d_in[3];
    const float* targets = (const float*)d_in[4];
    float* out = (float*)d_out;

    k_colmax<<<BB*(NN/CB), CB>>>(anchors, targets, sizes);
    k_classify<<<BB*(NN/256), 256>>>(logits, bregs, targets);
    k_select2<<<2*BB, 256>>>(out);
}

// round 14
// speedup vs baseline: 1.1952x; 1.0756x over previous
#include <cuda_runtime.h>
#include <stdint.h>

#define BB 4
#define AA 3
#define HH 168
#define WW 256
#define NN (HH*WW*AA)     // 129024
#define MM 32
#define NBINS 1024
#define CAPB 160
#define NPI 256
#define NPOSMAX 128
#define FG 0.7f
#define BG 0.3f
#define BETA (1.0f/9.0f)
#define CB 512            // colmax block size

// ------- scratch (device globals; zero at load; re-zeroed by select's last block)
__device__ unsigned            d_colmax[BB*MM];
__device__ int                 d_nin[BB];                 // compact inside-anchor count
__device__ float4              d_cA  [(size_t)BB*NN];     // compact anchors
__device__ int                 d_cIdx[(size_t)BB*NN];     // compact original index
__device__ int                 d_pcnt[BB*NBINS];
__device__ int                 d_ncnt[BB*NBINS];
__device__ float               d_psc [BB*NBINS];
__device__ float               d_psr [BB*NBINS];
__device__ float               d_nsc [BB*NBINS];
__device__ unsigned long long  d_pkey[(size_t)BB*NBINS*CAPB];
__device__ unsigned long long  d_nkey[(size_t)BB*NBINS*CAPB];
__device__ float               d_pvc [(size_t)BB*NBINS*CAPB];
__device__ float               d_pvr [(size_t)BB*NBINS*CAPB];
__device__ float               d_nvc [(size_t)BB*NBINS*CAPB];
__device__ float               d_ocls[2*BB];
__device__ float               d_oreg[2*BB];
__device__ int                 d_ocnt[2*BB];
__device__ int                 d_done;

// ---------------- threefry2x32 (exact JAX rotation/injection schedule) ------
__device__ __forceinline__ void tf2x32(unsigned k0, unsigned k1,
                                       unsigned x0, unsigned x1,
                                       unsigned &o0, unsigned &o1) {
    unsigned k2 = k0 ^ k1 ^ 0x1BD11BDAu;
    x0 += k0; x1 += k1;
#define TF_RND(r) { x0 += x1; x1 = (x1<<(r))|(x1>>(32-(r))); x1 ^= x0; }
    TF_RND(13) TF_RND(15) TF_RND(26) TF_RND(6)   x0 += k1; x1 += k2 + 1u;
    TF_RND(17) TF_RND(29) TF_RND(16) TF_RND(24)  x0 += k2; x1 += k0 + 2u;
    TF_RND(13) TF_RND(15) TF_RND(26) TF_RND(6)   x0 += k0; x1 += k1 + 3u;
    TF_RND(17) TF_RND(29) TF_RND(16) TF_RND(24)  x0 += k1; x1 += k2 + 4u;
    TF_RND(13) TF_RND(15) TF_RND(26) TF_RND(6)   x0 += k2; x1 += k0 + 5u;
#undef TF_RND
    o0 = x0; o1 = x1;
}

__device__ __forceinline__ float barea(float x1, float y1, float x2, float y2) {
    return __fmul_rn(__fadd_rn(__fsub_rn(x2, x1), 1.0f),
                     __fadd_rn(__fsub_rn(y2, y1), 1.0f));
}

// ------- kernel 1: per-target column max of IoU + inside-anchor compaction ---
// Running max tracked as (inter, S) where S = fl(aar+tar); u = fl(S - inter)
// only materializes at the epilogue/final division (bit-identical to ref).
// Tail reloads the anchor from smem so A0 isn't live across the hot loop.
__global__ __launch_bounds__(CB) void k_colmax(const float* __restrict__ anchors,
                                               const float* __restrict__ targets,
                                               const float* __restrict__ sizes) {
    const int BLK = NN / CB;          // 252
    int b = blockIdx.x / BLK;
    int tile = (blockIdx.x % BLK) * CB;
    int t = threadIdx.x, lane = t & 31, w = t >> 5;   // w: 0..15

    __shared__ float4 sA[CB];
    __shared__ float  sAr[CB];
    __shared__ int    swoff[CB/32];
    __shared__ int    sbase;

    {
        float4 A0 = reinterpret_cast<const float4*>(anchors)[(size_t)b*NN + tile + t];
        sA[t] = A0;
        sAr[t] = barea(A0.x, A0.y, A0.z, A0.w);
    }
    __syncthreads();

    float4 T0 = __ldg(&reinterpret_cast<const float4*>(targets)[b*MM + w*2 + 0]);
    float4 T1 = __ldg(&reinterpret_cast<const float4*>(targets)[b*MM + w*2 + 1]);
    float Tar0 = barea(T0.x, T0.y, T0.z, T0.w);
    float Tar1 = barea(T1.x, T1.y, T1.z, T1.w);
    float bi0 = 0.f, bS0 = 1.f, bi1 = 0.f, bS1 = 1.f;

    #pragma unroll 4
    for (int a = 0; a < CB/32; a++) {
        float4 X  = sA [a*32 + lane];
        float xar = sAr[a*32 + lane];
        {
            float iw = __fadd_rn(__fsub_rn(fminf(X.z, T0.z), fmaxf(X.x, T0.x)), 1.0f);
            float ih = __fadd_rn(__fsub_rn(fminf(X.w, T0.w), fmaxf(X.y, T0.y)), 1.0f);
            float inter = __fmul_rn(fmaxf(iw, 0.f), fmaxf(ih, 0.f));
            float S = __fadd_rn(xar, Tar0);
            if (inter*bS0 > bi0*S) { bi0 = inter; bS0 = S; }
        }
        {
            float iw = __fadd_rn(__fsub_rn(fminf(X.z, T1.z), fmaxf(X.x, T1.x)), 1.0f);
            float ih = __fadd_rn(__fsub_rn(fminf(X.w, T1.w), fmaxf(X.y, T1.y)), 1.0f);
            float inter = __fmul_rn(fmaxf(iw, 0.f), fmaxf(ih, 0.f));
            float S = __fadd_rn(xar, Tar1);
            if (inter*bS1 > bi1*S) { bi1 = inter; bS1 = S; }
        }
    }

    // margin epilogue: approx div + warp fmax; candidates do exact div + atomic
    {
        float u = __fsub_rn(bS0, bi0);                 // == ref's fl((a1+a2)-inter)
        float qa = (bi0 > 0.f) ? __fdividef(bi0, u) : 0.f;
        float m = qa;
        #pragma unroll
        for (int off = 16; off; off >>= 1)
            m = fmaxf(m, __shfl_xor_sync(0xFFFFFFFFu, m, off));
        if (bi0 > 0.f && qa >= __fmul_rn(m, 0.999998f)) {
            float q = __fdiv_rn(bi0, u);               // RN monotone
            atomicMax(&d_colmax[b*MM + w*2 + 0], __float_as_uint(q));
        }
    }
    {
        float u = __fsub_rn(bS1, bi1);
        float qa = (bi1 > 0.f) ? __fdividef(bi1, u) : 0.f;
        float m = qa;
        #pragma unroll
        for (int off = 16; off; off >>= 1)
            m = fmaxf(m, __shfl_xor_sync(0xFFFFFFFFu, m, off));
        if (bi1 > 0.f && qa >= __fmul_rn(m, 0.999998f)) {
            float q = __fdiv_rn(bi1, u);
            atomicMax(&d_colmax[b*MM + w*2 + 1], __float_as_uint(q));
        }
    }

    // tail: inside-anchor compaction, one atomic per block; anchor reloaded
    // from smem so it isn't live across the hot loop.
    float4 At = sA[t];
    float szh = __ldg(&sizes[b*2]), szw = __ldg(&sizes[b*2 + 1]);
    bool inside = (At.x >= 0.f) && (At.y >= 0.f) &&
                  (At.z <= szw - 1.0f) && (At.w <= szh - 1.0f);
    unsigned m = __ballot_sync(0xFFFFFFFFu, inside);
    if (lane == 0) swoff[w] = __popc(m);
    __syncthreads();
    if (t == 0) {
        int tot = 0;
        #pragma unroll
        for (int k = 0; k < CB/32; k++) { int c = swoff[k]; swoff[k] = tot; tot += c; }
        sbase = atomicAdd(&d_nin[b], tot);
    }
    __syncthreads();
    if (inside) {
        int pos = sbase + swoff[w] + __popc(m & ((1u << lane) - 1u));
        d_cA  [(size_t)b*NN + pos] = At;
        d_cIdx[(size_t)b*NN + pos] = tile + t;
    }
}

// ---------------- kernel 2: classify compacted inside anchors ---------------
// Per-j target data packed into two float4 smem arrays -> 2 LDS.128 per j.
__global__ void k_classify(const float* __restrict__ logits,
                           const float* __restrict__ bregs,
                           const float* __restrict__ targets) {
    const int BLK = NN / 256;
    int b = blockIdx.x / BLK;
    int slot = (blockIdx.x % BLK) * 256 + threadIdx.x;

    __shared__ float4 stt[MM];
    __shared__ float4 spp[MM];       // (Tar, slo, scol-bits, 0)
    __shared__ uint2 skeyb;
    __shared__ int sanyz, scnt2;
    if (threadIdx.x == 0) {
        unsigned o0, o1;
        tf2x32(0u, 42u, 0u, (unsigned)b, o0, o1);   // fold-like split of key 42
        skeyb = make_uint2(o0, o1);
        sanyz = 0;
        scnt2 = d_nin[b];
    }
    if (threadIdx.x < MM) {
        float4 t = reinterpret_cast<const float4*>(targets)[b*MM + threadIdx.x];
        stt[threadIdx.x] = t;
        unsigned cb = d_colmax[b*MM + threadIdx.x];
        float4 p;
        p.x = barea(t.x, t.y, t.z, t.w);
        p.y = __fmul_rn(__uint_as_float(cb), 0.999998f);
        p.z = __uint_as_float(cb);
        p.w = 0.f;
        spp[threadIdx.x] = p;
        if (cb == 0u) sanyz = 1;                    // benign race (all write 1)
    }
    __syncthreads();

    if (slot >= scnt2) return;                      // past compacted count
    float4 A = d_cA[(size_t)b*NN + slot];
    int i = d_cIdx[(size_t)b*NN + slot];

    bool restore = (sanyz != 0);
    float aar = barea(A.x, A.y, A.z, A.w);
    float bi = 0.f, bu = 1.f; int ori = 0;

    #pragma unroll 8
    for (int j = 0; j < MM; j++) {
        float4 T = stt[j];
        float4 P = spp[j];
        float iw = __fadd_rn(__fsub_rn(fminf(A.z, T.z), fmaxf(A.x, T.x)), 1.0f);
        float ih = __fadd_rn(__fsub_rn(fminf(A.w, T.w), fmaxf(A.y, T.y)), 1.0f);
        float inter = __fmul_rn(fmaxf(iw, 0.f), fmaxf(ih, 0.f));
        float u = __fsub_rn(__fadd_rn(aar, P.x), inter);
        if (inter*bu > bi*u) { bi = inter; bu = u; ori = j; }
        if (inter > 0.f && inter >= __fmul_rn(P.y, u)) {  // rare: exact div
            float q = __fdiv_rn(inter, u);
            restore = restore || (__float_as_uint(q) == __float_as_uint(P.z));
        }
    }
    float best = (bi > 0.f) ? __fdiv_rn(bi, bu) : 0.f;  // RN monotone

    bool pos = (best >= FG) || restore;
    bool neg = (!restore) && (best < BG);
    if (!pos && !neg) return;

    // exact JAX uniform priority: bits = o0^o1 of threefry(key_b, (0, i))
    unsigned o0, o1;
    tf2x32(skeyb.x, skeyb.y, 0u, (unsigned)i, o0, o1);
    unsigned prio = (o0 ^ o1) >> 9;
    unsigned long long kk = ((unsigned long long)prio << 32) | (0xFFFFFFFFu - (unsigned)i);
    int bin = (int)(prio >> 13);                    // 1024 bins

    int ai = i % AA; int hw = i / AA; int wx = hw % WW; int hy = hw / WW;
    float l = logits[(((size_t)b*AA + ai)*HH + hy)*WW + wx];
    float sp = log1pf(expf(-fabsf(l)));
    float cls = fmaxf(l, 0.f) + sp;          // BCE(l, 0)

    if (pos) {
        cls -= l;                            // BCE(l, 1)
        float ws = A.z - A.x + 1.0f, hs = A.w - A.y + 1.0f;
        float xc = A.x + 0.5f*ws,   yc = A.y + 0.5f*hs;
        float4 T = stt[ori];
        float tws = T.z - T.x + 1.0f, ths = T.w - T.y + 1.0f;
        float txc = T.x + 0.5f*tws,  tyc = T.y + 0.5f*ths;
        float off[4] = { (txc - xc)/ws, (tyc - yc)/hs, logf(tws/ws), logf(ths/hs) };
        float reg = 0.f;
        #pragma unroll
        for (int c = 0; c < 4; c++) {
            float br = bregs[(((size_t)b*4*AA + ai*4 + c)*HH + hy)*WW + wx];
            float d = fabsf(br - off[c]);
            reg += (d < BETA) ? 0.5f*d*d/BETA : d - 0.5f*BETA;
        }
        int idx = b*NBINS + bin;
        int c0 = atomicAdd(&d_pcnt[idx], 1);
        atomicAdd(&d_psc[idx], cls);
        atomicAdd(&d_psr[idx], reg);
        if (c0 < CAPB) {
            size_t e = (size_t)idx*CAPB + c0;
            d_pkey[e] = kk; d_pvc[e] = cls; d_pvr[e] = reg;
        }
    } else {
        int idx = b*NBINS + bin;
        int c0 = atomicAdd(&d_ncnt[idx], 1);
        atomicAdd(&d_nsc[idx], cls);
        if (c0 < CAPB) {
            size_t e = (size_t)idx*CAPB + c0;
            d_nkey[e] = kk; d_nvc[e] = cls;
        }
    }
}

// -------- kernel 3: exact top-K selection + finalize + scratch re-zero ------
__global__ void k_select2(float* __restrict__ out) {
    int b  = blockIdx.x >> 1;
    int ph = blockIdx.x & 1;           // 0 = positives, 1 = negatives
    int t = threadIdx.x;
    int lane = t & 31, wid = t >> 5;

    __shared__ int   scnt[NBINS];
    __shared__ float sredA[8], sredB[8];
    __shared__ int   swsum[8];
    __shared__ int   sint[4];
    __shared__ unsigned long long skey[CAPB];
    __shared__ float sv1[CAPB], sv2[CAPB];
    __shared__ int slast;

    const int*   cnt = (ph ? d_ncnt : d_pcnt) + b*NBINS;
    const float* s1  = (ph ? d_nsc  : d_psc ) + b*NBINS;
    const float* s2  = d_psr + b*NBINS;
    const unsigned long long* keyg = (ph ? d_nkey : d_pkey) + (size_t)b*NBINS*CAPB;
    const float* v1g = (ph ? d_nvc : d_pvc) + (size_t)b*NBINS*CAPB;
    const float* v2g = d_pvr + (size_t)b*NBINS*CAPB;

    int K;
    if (ph == 0) {
        K = NPOSMAX;
    } else {
        // num_pos = min(total positives, NPOSMAX): 1024 ints = 1 int4/thread
        int4 c = ((const int4*)(d_pcnt + b*NBINS))[t];
        int s = c.x + c.y + c.z + c.w;
        #pragma unroll
        for (int off = 16; off; off >>= 1) s += __shfl_xor_sync(0xFFFFFFFFu, s, off);
        if (lane == 0) swsum[wid] = s;
        __syncthreads();
        if (t == 0) { int tot = 0; for (int w = 0; w < 8; w++) tot += swsum[w]; sint[3] = tot; }
        __syncthreads();
        int np = sint[3]; if (np > NPOSMAX) np = NPOSMAX;
        K = NPI - np;
        __syncthreads();
    }

    // thread t owns 4 bins [base, base+4), base descending with t
    int base = NBINS - 4*(t+1);
    int4 c4 = *(const int4*)(cnt + base);
    scnt[base+0] = c4.x; scnt[base+1] = c4.y; scnt[base+2] = c4.z; scnt[base+3] = c4.w;
    int cs = c4.x + c4.y + c4.z + c4.w;

    int v = cs;
    #pragma unroll
    for (int off = 1; off < 32; off <<= 1) {
        int n = __shfl_up_sync(0xFFFFFFFFu, v, off);
        if (lane >= off) v += n;
    }
    if (lane == 31) swsum[wid] = v;
    __syncthreads();
    if (t < 8) {
        int x = swsum[t];
        #pragma unroll
        for (int off = 1; off < 8; off <<= 1) {
            int n = __shfl_up_sync(0x000000FFu, x, off);
            if (t >= off) x += n;
        }
        swsum[t] = x;
    }
    __syncthreads();
    int incl  = v + (wid ? swsum[wid-1] : 0);
    int excl  = incl - cs;
    int total = swsum[7];

    if (t == 0) { sint[0] = -1; sint[1] = 0; }
    __syncthreads();
    if (total > K && excl < K && incl >= K) {     // exactly one thread
        int cum = excl;
        #pragma unroll
        for (int k = 3; k >= 0; k--) {            // descending bin order
            int cc = scnt[base + k];
            if (cum + cc >= K) { sint[0] = base + k; sint[1] = K - cum; break; }
            cum += cc;
        }
    }
    __syncthreads();
    int binT = sint[0], Kp = sint[1];

    // whole-bin sums for bins strictly above the threshold bin
    float a1 = 0.f, a2 = 0.f;
    {
        float4 x = *(const float4*)(s1 + base);
        if (base + 0 > binT) a1 += x.x;
        if (base + 1 > binT) a1 += x.y;
        if (base + 2 > binT) a1 += x.z;
        if (base + 3 > binT) a1 += x.w;
        if (ph == 0) {
            float4 y = *(const float4*)(s2 + base);
            if (base + 0 > binT) a2 += y.x;
            if (base + 1 > binT) a2 += y.y;
            if (base + 2 > binT) a2 += y.z;
            if (base + 3 > binT) a2 += y.w;
        }
    }

    // boundary bin: exact rank selection on unique keys
    if (binT >= 0) {
        int nt = cnt[binT]; if (nt > CAPB) nt = CAPB;
        size_t bb2 = (size_t)binT * CAPB;
        for (int e = t; e < nt; e += 256) {
            skey[e] = keyg[bb2 + e];
            sv1[e]  = v1g[bb2 + e];
            if (ph == 0) sv2[e] = v2g[bb2 + e];
        }
        __syncthreads();
        for (int e = t; e < nt; e += 256) {
            unsigned long long ke = skey[e];
            int rank = 0;
            for (int q = 0; q < nt; q++) rank += (skey[q] > ke);
            if (rank < Kp) { a1 += sv1[e]; if (ph == 0) a2 += sv2[e]; }
        }
    }
    __syncthreads();

    // shfl-based block reduction of (a1, a2)
    #pragma unroll
    for (int off = 16; off; off >>= 1) {
        a1 += __shfl_xor_sync(0xFFFFFFFFu, a1, off);
        a2 += __shfl_xor_sync(0xFFFFFFFFu, a2, off);
    }
    if (lane == 0) { sredA[wid] = a1; sredB[wid] = a2; }
    __syncthreads();

    if (t == 0) {
        float r1 = 0.f, r2 = 0.f;
        #pragma unroll
        for (int w2 = 0; w2 < 8; w2++) { r1 += sredA[w2]; r2 += sredB[w2]; }
        d_ocls[blockIdx.x] = r1;
        d_oreg[blockIdx.x] = (ph == 0) ? r2 : 0.f;
        d_ocnt[blockIdx.x] = (total < K) ? total : K;
        __threadfence();
        int done = atomicAdd(&d_done, 1);
        slast = (done == 2*BB - 1);
    }
    __syncthreads();

    // last block: finalize output + restore scratch to zero for the next replay
    if (slast) {
        __threadfence();
        int4 zi = make_int4(0,0,0,0);
        float4 zf = make_float4(0.f,0.f,0.f,0.f);
        #pragma unroll
        for (int g = 0; g < (BB*NBINS/4)/256; g++) {
            int idx = g*256 + t;
            reinterpret_cast<int4*>(d_pcnt)[idx]   = zi;
            reinterpret_cast<int4*>(d_ncnt)[idx]   = zi;
            reinterpret_cast<float4*>(d_psc)[idx]  = zf;
            reinterpret_cast<float4*>(d_psr)[idx]  = zf;
            reinterpret_cast<float4*>(d_nsc)[idx]  = zf;
        }
        if (t < BB*MM) d_colmax[t] = 0u;
        if (t < BB) d_nin[t] = 0;
        if (t == 0) {
            d_done = 0;
            float cs = 0.f, rs = 0.f; int cn = 0;
            #pragma unroll
            for (int q = 0; q < 2*BB; q++) { cs += d_ocls[q]; rs += d_oreg[q]; cn += d_ocnt[q]; }
            float tot = (float)cn;
            out[0] = cs / tot;
            out[1] = rs / tot;
        }
    }
}

// ---------------- launch ----------------------------------------------------
extern "C" void kernel_launch(void* const* d_in, const int* in_sizes, int n_in,
                              void* d_out, int out_size) {
    const float* anchors = (const float*)d_in[0];
    const float* logits  = (const float*)d_in[1];
    const float* bregs   = (const float*)d_in[2];
    const float* sizes   = (const float*)d_in[3];
    const float* targets = (const float*)d_in[4];
    float* out = (float*)d_out;

    k_colmax<<<BB*(NN/CB), CB>>>(anchors, targets, sizes);
    k_classify<<<BB*(NN/256), 256>>>(logits, bregs, targets);
    k_select2<<<2*BB, 256>>>(out);
}